// round 5
// baseline (speedup 1.0000x reference)
#include <cuda_runtime.h>
#include <cstdint>

// WHTConv2D: y = FWHT2( soft_threshold(W @ (v * FWHT2(x)), T) + FWHT2(x) ) / (H*W)
// x[32,64,128,128] f32, W[64,64], v[128,128], T[128,128]
// Identity: y = FWHT2( soft_threshold(W@(v*f2),T) + f2 ) / 16384,  f2 = FWHT2(x)

#define HW      16384
#define NPLANES 2048

// 128 MB scratch (static __device__ global: no runtime allocation)
__device__ float g_scratch[33554432];

// ---------------- packed f32x2 FMA (Blackwell FFMA2; PTX-only form) --------
__device__ __forceinline__ unsigned long long ffma2(
    unsigned long long a, unsigned long long b, unsigned long long c)
{
    unsigned long long d;
    asm("fma.rn.f32x2 %0, %1, %2, %3;" : "=l"(d) : "l"(a), "l"(b), "l"(c));
    return d;
}
union U64F2 { unsigned long long u; float2 f; };

// ---------------- shuffle-free FWHT2 (verified R4: 55.6us, keep) -----------
__device__ __forceinline__ void fwht_regs32(float* d) {
#pragma unroll
    for (int s = 1; s <= 16; s <<= 1) {
#pragma unroll
        for (int r = 0; r < 32; r++) {
            if (!(r & s)) {
                int q = r | s;
                float a = d[r] + d[q];
                d[q] = d[r] - d[q];
                d[r] = a;
            }
        }
    }
}
__device__ __forceinline__ void fwht_regs16x2(float* d) {
#pragma unroll
    for (int s = 1; s <= 8; s <<= 1) {
#pragma unroll
        for (int r = 0; r < 32; r++) {
            if (!(r & s)) {
                int q = r | s;
                float a = d[r] + d[q];
                d[q] = d[r] - d[q];
                d[r] = a;
            }
        }
    }
}

__global__ void __launch_bounds__(512)
fwht2_kernel(const float* __restrict__ in, float* __restrict__ out, float scale)
{
    extern __shared__ float sm[];   // 16384 floats = 64 KB
    const long base = (long)blockIdx.x * HW;
    const int t = threadIdx.x;

    float d[32];

#pragma unroll
    for (int r = 0; r < 32; r++) d[r] = in[base + r * 512 + t];

    fwht_regs32(d);   // bits 13..9

#pragma unroll
    for (int r = 0; r < 32; r++) sm[(r * 512 + t) ^ ((r & 1) << 4)] = d[r];
    __syncthreads();

    {
        const int hi = t >> 4;
        const int lo = t & 15;
        const int x1 = (hi & 1) << 4;
        const int eb = hi * 512 + lo;
#pragma unroll
        for (int r = 0; r < 32; r++) d[r] = sm[(eb + r * 16) ^ x1];
    }
    __syncthreads();

    fwht_regs32(d);   // bits 8..4

    {
        const int hi = t >> 4;
        const int lo = t & 15;
        const int x1 = (hi & 1) << 4;
        const int eb = hi * 512 + lo;
#pragma unroll
        for (int r = 0; r < 32; r++) sm[((eb + r * 16) ^ (r >> 1)) ^ x1] = d[r];
    }
    __syncthreads();

    {
        const int hb = (t >> 5) << 10;
        const int mb = (t & 31) << 4;
        const int x2 = (t & 31) >> 1;
        const int eb = hb | mb;
#pragma unroll
        for (int r = 0; r < 32; r++)
            d[r] = sm[((eb | ((r >> 4) << 9) | (r & 15)) ^ x2) ^ ((r >> 4) << 4)];
    }
    __syncthreads();

    fwht_regs16x2(d); // bits 3..0

    {
        const int hb = (t >> 5) << 10;
        const int mb = (t & 31) << 4;
        const int x2 = (t & 31) >> 1;
        const int eb = hb | mb;
#pragma unroll
        for (int r = 0; r < 32; r++)
            sm[(eb | ((r >> 4) << 9) | (r & 15)) ^ x2] = d[r];
    }
    __syncthreads();

    {
        const int x3 = (t >> 5) & 15;
#pragma unroll
        for (int r = 0; r < 32; r++)
            out[base + r * 512 + t] = sm[(r * 512 + t) ^ x3] * scale;
    }
}

// ---------------- channel mix: packed-f32x2 GEMM + fused epilogue ----------
// Grid (64, 32): tile = all 64 chans x 256 pixels, in-place on g_scratch.
// Warp w -> 8 output channels (W loads are warp-uniform smem broadcasts of
// pre-duplicated {w,w} pairs). Lane l -> 8 pixels = 4 f32x2 pairs.
// Per c: 4 broadcast LDS + 2 LDS.128 + 32 FFMA2 (vs 4 LDS + 64 FFMA before).
__global__ void __launch_bounds__(256, 2)
mix_kernel(const float* __restrict__ Wm,
           const float* __restrict__ vmap, const float* __restrict__ Tmap)
{
    extern __shared__ float smbuf[];
    float2* Wd = reinterpret_cast<float2*>(smbuf);   // [c][o] duplicated, 32 KB
    float*  Xs = smbuf + 8192;                       // [c][p] 64x256, 64 KB
    const int t = threadIdx.x;
    const int b = blockIdx.y;
    const int pbase = blockIdx.x << 8;

    // Wd[c][o] = {W[o][c], W[o][c]}
#pragma unroll
    for (int i = 0; i < 16; i++) {
        int idx = t + (i << 8);
        int o = idx >> 6, c = idx & 63;
        float w = __ldg(Wm + idx);
        Wd[(c << 6) + o] = make_float2(w, w);
    }
    // Xs[c][p] = f2[b,c,pbase+p] (float4 coalesced)
#pragma unroll
    for (int i = 0; i < 16; i++) {
        int f4i = t + (i << 8);
        int c = f4i >> 6, col = f4i & 63;
        reinterpret_cast<float4*>(Xs)[(c << 6) + col] =
            *reinterpret_cast<const float4*>(g_scratch + (long)(b * 64 + c) * HW + pbase + (col << 2));
    }
    __syncthreads();

    const int to = (t >> 5) << 3;   // warp-uniform: 8 output channels
    const int tp = (t & 31) << 3;   // per-lane: 8 pixels (4 pairs)

    unsigned long long acc[8][4];
#pragma unroll
    for (int o = 0; o < 8; o++)
#pragma unroll
        for (int k = 0; k < 4; k++) acc[o][k] = 0ull;

#pragma unroll 4
    for (int c = 0; c < 64; c++) {
        const ulonglong2* wrow = reinterpret_cast<const ulonglong2*>(&Wd[(c << 6) + to]);
        ulonglong2 w01 = wrow[0];   // broadcast LDS.128: pairs for o, o+1
        ulonglong2 w23 = wrow[1];
        ulonglong2 w45 = wrow[2];
        ulonglong2 w67 = wrow[3];
        const ulonglong2* xrow = reinterpret_cast<const ulonglong2*>(&Xs[(c << 8) + tp]);
        ulonglong2 xa = xrow[0];    // pixel pairs 0,1
        ulonglong2 xb = xrow[1];    // pixel pairs 2,3
        unsigned long long wv[8] = {w01.x, w01.y, w23.x, w23.y, w45.x, w45.y, w67.x, w67.y};
        unsigned long long xp[4] = {xa.x, xa.y, xb.x, xb.y};
#pragma unroll
        for (int o = 0; o < 8; o++)
#pragma unroll
            for (int k = 0; k < 4; k++)
                acc[o][k] = ffma2(wv[o], xp[k], acc[o][k]);
    }

    // Epilogue: v-scale, soft-threshold, residual, store
    float vv[8], tt[8];
#pragma unroll
    for (int p = 0; p < 8; p++) {
        vv[p] = __ldg(vmap + pbase + tp + p);
        tt[p] = fmaxf(__ldg(Tmap + pbase + tp + p), 0.0f);
    }
#pragma unroll
    for (int o = 0; o < 8; o++) {
        const int og = to + o;
        float res[8];
        *reinterpret_cast<float4*>(res)     = *reinterpret_cast<const float4*>(&Xs[(og << 8) + tp]);
        *reinterpret_cast<float4*>(res + 4) = *reinterpret_cast<const float4*>(&Xs[(og << 8) + tp + 4]);
        float outv[8];
#pragma unroll
        for (int k = 0; k < 4; k++) {
            U64F2 cv; cv.u = acc[o][k];
#pragma unroll
            for (int h = 0; h < 2; h++) {
                int p = 2 * k + h;
                float a = (h == 0) ? cv.f.x : cv.f.y;
                float z = vv[p] * a;
                float m = fmaxf(fabsf(z) - tt[p], 0.0f);
                uint32_t sgn = __float_as_uint(z) & 0x80000000u;
                outv[p] = __uint_as_float(__float_as_uint(m) | sgn) + res[p];
            }
        }
        float* dst = g_scratch + (long)(b * 64 + og) * HW + pbase + tp;
        *reinterpret_cast<float4*>(dst)     = *reinterpret_cast<float4*>(outv);
        *reinterpret_cast<float4*>(dst + 4) = *reinterpret_cast<float4*>(outv + 4);
    }
}

extern "C" void kernel_launch(void* const* d_in, const int* in_sizes, int n_in,
                              void* d_out, int out_size)
{
    (void)in_sizes; (void)n_in; (void)out_size;
    const float* x  = (const float*)d_in[0];
    const float* Wm = (const float*)d_in[1];
    const float* v  = (const float*)d_in[2];
    const float* T  = (const float*)d_in[3];
    float* y = (float*)d_out;

    float* scratch;
    cudaGetSymbolAddress((void**)&scratch, g_scratch);

    const int fwht_smem = HW * sizeof(float);                 // 65536 B
    const int mix_smem  = (8192 + 64 * 256) * sizeof(float);  // 98304 B
    cudaFuncSetAttribute(fwht2_kernel, cudaFuncAttributeMaxDynamicSharedMemorySize, fwht_smem);
    cudaFuncSetAttribute(mix_kernel,   cudaFuncAttributeMaxDynamicSharedMemorySize, mix_smem);

    // K1: g_scratch = FWHT2(x)
    fwht2_kernel<<<NPLANES, 512, fwht_smem>>>(x, scratch, 1.0f);
    // K2: g_scratch = soft_threshold(W @ (v*f2), T) + f2   (in-place)
    mix_kernel<<<dim3(HW / 256, 32), 256, mix_smem>>>(Wm, v, T);
    // K3: y = FWHT2(g_scratch) / 16384
    fwht2_kernel<<<NPLANES, 512, fwht_smem>>>(scratch, y, 1.0f / 16384.0f);
}